// round 9
// baseline (speedup 1.0000x reference)
#include <cuda_runtime.h>
#include <cstdint>

// CoExCostVolume: cost[b,d,h,w] = sum_c x[b,c,h,w]*y[b,c,h,w-d], zero for w<d.
// B=8, C=96, H=128, W=416, D=49.
//
// One CTA per (b,h) row, 448 threads = 7 warp-pairs; pair g owns d in
// [7g,7g+7), lane index l (<52) owns w in [8l,8l+8).
// All fma.rn.f32x2 operands load DIRECTLY as ulonglong2 from smem (no mov.b64):
// y is stored twice, once normal (even-parity pairs) and once shifted by one
// element (odd-parity pairs). XOR swizzle S(p)=p^((p>>3)&4) keeps 16B alignment
// and is conflict-free for the lane-stride-8 LDS.128 pattern.
// cp.async 3-buffer depth-2 pipeline, 8 chunks of 12 channels.

#define B_DIM 8
#define C_DIM 96
#define H_DIM 128
#define W_DIM 416
#define D_DIM 49
#define HW (H_DIM * W_DIM)

#define CC 12
#define NC 8
#define NBUF 3
#define XSTRIDE 448            // >= SW(415)+1, mult of 32
#define YSTRIDE 480            // covers SW(q) for q<=467, mult of 32
#define XSZ (CC * XSTRIDE)     // 5376
#define BUFSZ (XSZ + 2 * CC * YSTRIDE)   // 16896 floats = 67584 B
#define NTHREADS 448
#define SMEM_BYTES (NBUF * BUFSZ * 4)    // 202752

typedef unsigned long long ull;

__device__ __forceinline__ int SW(int p) { return p ^ ((p >> 3) & 4); }

__device__ __forceinline__ void cp8(float* dst_smem, const float* src) {
    unsigned s = (unsigned)__cvta_generic_to_shared(dst_smem);
    asm volatile("cp.async.ca.shared.global [%0], [%1], 8;\n" ::"r"(s), "l"(src));
}
__device__ __forceinline__ void cp4(float* dst_smem, const float* src) {
    unsigned s = (unsigned)__cvta_generic_to_shared(dst_smem);
    asm volatile("cp.async.ca.shared.global [%0], [%1], 4;\n" ::"r"(s), "l"(src));
}
__device__ __forceinline__ void fma2(ull& d, ull a, ull b) {
    asm("fma.rn.f32x2 %0, %1, %2, %0;" : "+l"(d) : "l"(a), "l"(b));
}
__device__ __forceinline__ float2 upk(ull p) {
    float2 v; asm("mov.b64 {%0, %1}, %2;" : "=f"(v.x), "=f"(v.y) : "l"(p)); return v;
}

// One 12-channel chunk. R = q0 & 3 (warp-uniform window phase).
// ev[k] = y-pair at padded coord EA+2k (normal copy), od[k] = pair at EA+2k+1
// (shifted copy). py[u] (coord q0+u) selected by parity at compile time.
template <int R>
__device__ __forceinline__ void accum(const float* __restrict__ buf,
                                      int xo0, int xo1,
                                      const int* __restrict__ eo,
                                      const int* __restrict__ oo,
                                      ull* __restrict__ acc) {
#pragma unroll 4
    for (int c = 0; c < CC; c++) {
        const float* xb = buf + c * XSTRIDE;
        const float* yb = buf + c * YSTRIDE;
        ulonglong2 xv0 = *(const ulonglong2*)(xb + xo0);
        ulonglong2 xv1 = *(const ulonglong2*)(xb + xo1);
        ull px[4] = {xv0.x, xv0.y, xv1.x, xv1.y};

        ull ev[8], od[8];
        if (R != 3) { ulonglong2 t = *(const ulonglong2*)(yb + eo[0]); ev[0] = t.x; ev[1] = t.y; }
        { ulonglong2 t = *(const ulonglong2*)(yb + eo[1]); ev[2] = t.x; ev[3] = t.y; }
        { ulonglong2 t = *(const ulonglong2*)(yb + eo[2]); ev[4] = t.x; ev[5] = t.y; }
        { ulonglong2 t = *(const ulonglong2*)(yb + eo[3]); ev[6] = t.x; ev[7] = t.y; }
        { ulonglong2 t = *(const ulonglong2*)(yb + oo[0]); od[0] = t.x; od[1] = t.y; }
        { ulonglong2 t = *(const ulonglong2*)(yb + oo[1]); od[2] = t.x; od[3] = t.y; }
        { ulonglong2 t = *(const ulonglong2*)(yb + oo[2]); od[4] = t.x; od[5] = t.y; }
        if (R != 0) { ulonglong2 t = *(const ulonglong2*)(yb + oo[3]); od[6] = t.x; od[7] = t.y; }

#pragma unroll
        for (int i = 0; i < 7; i++)
#pragma unroll
            for (int j = 0; j < 4; j++) {
                const int u = 2 * j + 6 - i;           // py coord offset, 0..12
                ull py = ((R + u) & 1) ? od[(R + u - 1) >> 1] : ev[(R + u) >> 1];
                fma2(acc[i * 4 + j], px[j], py);
            }
    }
}

__global__ void __launch_bounds__(NTHREADS, 1)
coex_cost_kernel(const float* __restrict__ x,
                 const float* __restrict__ y,
                 float* __restrict__ out) {
    extern __shared__ float sm[];

    const int bid = blockIdx.x;
    const int b = bid >> 7;
    const int h = bid & 127;
    const int tid = threadIdx.x;
    const int wid = tid >> 5;
    const int lane = tid & 31;
    const int g = wid >> 1;                 // 0..6 d-group (warp-uniform)
    const int l = ((wid & 1) << 5) + lane;  // 0..63
    const bool active = (l < 52);
    const int d0 = 7 * g;
    const int w0 = 8 * l;

    const long rowb = ((long)(b * C_DIM) * H_DIM + h) * W_DIM;

    // ---- zero y pads once: 2*CC rows (ys then ys2) x coords [0,48), all bufs.
    // SW maps [0,48) into [0,48) so raw zeroing covers the swizzled image.
    for (int i = tid; i < NBUF * 2 * CC * 48; i += NTHREADS) {
        int buf = i / (2 * CC * 48);
        int r = i - buf * (2 * CC * 48);
        int rr = r / 48;
        int p = r - rr * 48;
        sm[buf * BUFSZ + XSZ + rr * YSTRIDE + p] = 0.0f;
    }

    // ---- per-thread addresses ----
    const int q0 = w0 + 42 - d0;            // window base, >= 0
    const int R = q0 & 3;                    // warp-uniform
    const int EA = q0 - R;                   // 4-aligned
    const int xo0 = SW(w0);
    const int xo1 = SW(w0 + 4);
    int eo[4], oo[4];
#pragma unroll
    for (int j = 0; j < 4; j++) {
        eo[j] = XSZ + SW(EA + 4 * j);
        oo[j] = XSZ + CC * YSTRIDE + SW(EA + 4 * j);
    }

    ull acc[28];
#pragma unroll
    for (int i = 0; i < 28; i++) acc[i] = 0ull;

    // ---- staging ----
    auto stage = [&](int k) {
        const long co = rowb + (long)k * CC * HW;
        float* bx = sm + (k % NBUF) * BUFSZ;
        float* by = bx + XSZ;
        float* b2 = by + CC * YSTRIDE;
#pragma unroll 1
        for (int idx = tid; idx < CC * 208; idx += NTHREADS) {
            int c = idx / 208;
            int p = (idx - c * 208) * 2;
            const long gs = co + (long)c * HW + p;
            cp8(bx + c * XSTRIDE + SW(p), x + gs);
            cp8(by + c * YSTRIDE + SW(48 + p), y + gs);
        }
        // shifted copy: ys2 coord 47+w  <=  y[w]
#pragma unroll 1
        for (int idx = tid; idx < CC * 416; idx += NTHREADS) {
            int c = idx / 416;
            int w = idx - c * 416;
            cp4(b2 + c * YSTRIDE + SW(47 + w), y + co + (long)c * HW + w);
        }
    };

    stage(0); asm volatile("cp.async.commit_group;\n");
    stage(1); asm volatile("cp.async.commit_group;\n");

#pragma unroll 1
    for (int k = 0; k < NC; k++) {
        if (k < NC - 1) asm volatile("cp.async.wait_group 1;\n" ::: "memory");
        else            asm volatile("cp.async.wait_group 0;\n" ::: "memory");
        __syncthreads();

        if (k + 2 < NC) {
            stage(k + 2);
            asm volatile("cp.async.commit_group;\n");
        }

        const float* buf = sm + (k % NBUF) * BUFSZ;
        if (active) {
            switch (R) {
                case 0: accum<0>(buf, xo0, xo1, eo, oo, acc); break;
                case 1: accum<1>(buf, xo0, xo1, eo, oo, acc); break;
                case 2: accum<2>(buf, xo0, xo1, eo, oo, acc); break;
                default: accum<3>(buf, xo0, xo1, eo, oo, acc); break;
            }
        }
    }

    // ---- stores: 7 d x 8 w per active thread ----
    if (active) {
#pragma unroll
        for (int i = 0; i < 7; i++) {
            const int d = d0 + i;
            float* o = out + (((long)b * D_DIM + d) * H_DIM + h) * W_DIM + w0;
            float2 p0 = upk(acc[i * 4 + 0]);
            float2 p1 = upk(acc[i * 4 + 1]);
            float2 p2 = upk(acc[i * 4 + 2]);
            float2 p3 = upk(acc[i * 4 + 3]);
            *reinterpret_cast<float4*>(o) = make_float4(p0.x, p0.y, p1.x, p1.y);
            *reinterpret_cast<float4*>(o + 4) = make_float4(p2.x, p2.y, p3.x, p3.y);
        }
    }
}

extern "C" void kernel_launch(void* const* d_in, const int* in_sizes, int n_in,
                              void* d_out, int out_size) {
    const float* x = (const float*)d_in[0];
    const float* y = (const float*)d_in[1];
    float* out = (float*)d_out;

    cudaFuncSetAttribute(coex_cost_kernel,
                         cudaFuncAttributeMaxDynamicSharedMemorySize, SMEM_BYTES);

    coex_cost_kernel<<<B_DIM * H_DIM, NTHREADS, SMEM_BYTES>>>(x, y, out);
}

// round 11
// speedup vs baseline: 1.3999x; 1.3999x over previous
#include <cuda_runtime.h>
#include <cstdint>

// CoExCostVolume: cost[b,d,h,w] = sum_c x[b,c,h,w]*y[b,c,h,w-d], zero for w<d.
// B=8, C=96, H=128, W=416, D=49.
//
// One CTA per (b,h) row, 448 threads = 7 warp-pairs; pair g owns d in
// [7g,7g+7), lane index l (<52) owns w in [8l,8l+8).
// XOR swizzle S(p)=p^((p>>3)&4): 16B-alignment preserving, conflict-free for
// the lane-stride-8-float LDS.128 pattern at any 4-aligned base.
// NOTE: SW(w0+4) != SW(w0)+4 — every 16B vector must use its own swizzled
// address (R10's xb+4 shortcut swapped x halves on half the lanes).
// y window loaded as dual ulonglong2/float4 views: even-parity fma.rn.f32x2
// operand pairs are the ull components (no movs); only odd-parity pairs are
// built with mov.b64. x pairs likewise mov-free.
// cp.async(8B) 3-buffer depth-2 pipeline, 6 chunks of 16 channels, additive
// staging index advance (no div/mod in the staging loop).

#define B_DIM 8
#define C_DIM 96
#define H_DIM 128
#define W_DIM 416
#define D_DIM 49
#define HW (H_DIM * W_DIM)

#define CC 16
#define NC 6
#define NBUF 3
#define XSTRIDE 448
#define YSTRIDE 480
#define XSZ (CC * XSTRIDE)
#define BUFSZ (XSZ + CC * YSTRIDE)
#define NTHREADS 448
#define SMEM_BYTES (NBUF * BUFSZ * 4)   // 178176

typedef unsigned long long ull;

__device__ __forceinline__ int SW(int p) { return p ^ ((p >> 3) & 4); }

__device__ __forceinline__ void cp8(float* dst_smem, const float* src) {
    unsigned s = (unsigned)__cvta_generic_to_shared(dst_smem);
    asm volatile("cp.async.ca.shared.global [%0], [%1], 8;\n" ::"r"(s), "l"(src));
}
__device__ __forceinline__ ull pk(float lo, float hi) {
    ull r; asm("mov.b64 %0, {%1, %2};" : "=l"(r) : "f"(lo), "f"(hi)); return r;
}
__device__ __forceinline__ void fma2(ull& d, ull a, ull b) {
    asm("fma.rn.f32x2 %0, %1, %2, %0;" : "+l"(d) : "l"(a), "l"(b));
}
__device__ __forceinline__ float2 upk(ull p) {
    float2 v; asm("mov.b64 {%0, %1}, %2;" : "=f"(v.x), "=f"(v.y) : "l"(p)); return v;
}

// One 16-channel chunk. R = q0&3 (warp-uniform window phase).
// Window scalars live at float offsets [R, R+13] of the loaded 4*NV floats.
// py pair at offset o: even o -> ull component (free); odd o -> pk mov.
template <int R>
__device__ __forceinline__ void accum(const float* __restrict__ buf,
                                      int xo0, int xo1,
                                      const int* __restrict__ yo,
                                      ull* __restrict__ acc) {
    constexpr int NV = (R == 3) ? 5 : 4;
#pragma unroll 4
    for (int c = 0; c < CC; c++) {
        ulonglong2 xa = *(const ulonglong2*)(buf + xo0 + c * XSTRIDE);
        ulonglong2 xc = *(const ulonglong2*)(buf + xo1 + c * XSTRIDE);
        ull px[4] = {xa.x, xa.y, xc.x, xc.y};

        ull ev[2 * NV];
        float f[4 * NV];
#pragma unroll
        for (int v = 0; v < NV; v++) {
            const float* p = buf + yo[v] + c * YSTRIDE;
            ulonglong2 u = *(const ulonglong2*)p;
            float4 q = *(const float4*)p;   // same address: CSE to one LDS.128
            ev[2 * v] = u.x; ev[2 * v + 1] = u.y;
            f[4 * v + 0] = q.x; f[4 * v + 1] = q.y;
            f[4 * v + 2] = q.z; f[4 * v + 3] = q.w;
        }

        ull od[8];
#pragma unroll
        for (int m = 0; m < 8; m++) {
            const int o = 2 * m + 1;
            if (o >= R && o <= R + 12) od[m] = pk(f[o], f[o + 1]);
        }

#pragma unroll
        for (int i = 0; i < 7; i++)
#pragma unroll
            for (int j = 0; j < 4; j++) {
                const int o = R + 2 * j + 6 - i;    // pair offset, R..R+12
                ull py = (o & 1) ? od[o >> 1] : ev[o >> 1];
                fma2(acc[i * 4 + j], px[j], py);
            }
    }
}

__global__ void __launch_bounds__(NTHREADS, 1)
coex_cost_kernel(const float* __restrict__ x,
                 const float* __restrict__ y,
                 float* __restrict__ out) {
    extern __shared__ float sm[];

    const int bid = blockIdx.x;
    const int b = bid >> 7;
    const int h = bid & 127;
    const int tid = threadIdx.x;
    const int wid = tid >> 5;
    const int lane = tid & 31;
    const int g = wid >> 1;                 // 0..6 d-group (warp-uniform)
    const int l = ((wid & 1) << 5) + lane;  // 0..63
    const bool active = (l < 52);
    const int d0 = 7 * g;
    const int w0 = 8 * l;

    const long rowb = ((long)(b * C_DIM) * H_DIM + h) * W_DIM;

    // ---- zero y left-pad once (all buffers); SW is a bijection on [0,48) ----
    for (int i = tid; i < NBUF * CC * 48; i += NTHREADS) {
        int buf = i / (CC * 48);
        int rest = i - buf * (CC * 48);
        int c = rest / 48;
        int p = rest - c * 48;
        sm[buf * BUFSZ + XSZ + c * YSTRIDE + p] = 0.0f;
    }

    // ---- per-thread addresses ----
    const int w0c = active ? w0 : 0;
    const int q0c = active ? (w0 + 42 - d0) : 0;   // window base, >= 0
    const int R = q0c & 3;                          // warp-uniform
    const int qa = q0c - R;
    const int xo0 = SW(w0c);
    const int xo1 = SW(w0c + 4);                    // own swizzle — NOT xo0+4
    int yo[5];
#pragma unroll
    for (int v = 0; v < 5; v++) yo[v] = XSZ + SW(qa + 4 * v);

    ull acc[28];
#pragma unroll
    for (int i = 0; i < 28; i++) acc[i] = 0ull;

    // ---- staging: additive (c, p) advance, 8B cp.async for x and y ----
    const int c0 = tid / 208;            // 0..2
    const int p0 = tid - c0 * 208;       // float2 index within row
    auto stage = [&](int k) {
        float* bx = sm + (k % NBUF) * BUFSZ;
        float* by = bx + XSZ;
        const float* xg = x + rowb + (long)k * CC * HW;
        const float* yg = y + rowb + (long)k * CC * HW;
        int c = c0, p = p0;
#pragma unroll 1
        for (int it = 0; it < 8; it++) {
            if (c < CC) {
                int w = 2 * p;
                long gsrc = (long)c * HW + w;
                cp8(bx + c * XSTRIDE + SW(w), xg + gsrc);
                cp8(by + c * YSTRIDE + SW(48 + w), yg + gsrc);
            }
            c += 2; p += 32;                 // +448 float2 = 2 rows + 32
            if (p >= 208) { p -= 208; c += 1; }
        }
    };

    stage(0); asm volatile("cp.async.commit_group;\n");
    stage(1); asm volatile("cp.async.commit_group;\n");

#pragma unroll 1
    for (int k = 0; k < NC; k++) {
        if (k < NC - 1) asm volatile("cp.async.wait_group 1;\n" ::: "memory");
        else            asm volatile("cp.async.wait_group 0;\n" ::: "memory");
        __syncthreads();

        if (k + 2 < NC) {
            stage(k + 2);
            asm volatile("cp.async.commit_group;\n");
        }

        const float* buf = sm + (k % NBUF) * BUFSZ;
        if (active) {
            switch (R) {
                case 0: accum<0>(buf, xo0, xo1, yo, acc); break;
                case 1: accum<1>(buf, xo0, xo1, yo, acc); break;
                case 2: accum<2>(buf, xo0, xo1, yo, acc); break;
                default: accum<3>(buf, xo0, xo1, yo, acc); break;
            }
        }
    }

    // ---- stores: 7 d x 8 w per active thread ----
    if (active) {
#pragma unroll
        for (int i = 0; i < 7; i++) {
            const int d = d0 + i;
            float* o = out + (((long)b * D_DIM + d) * H_DIM + h) * W_DIM + w0;
            float2 p0v = upk(acc[i * 4 + 0]);
            float2 p1v = upk(acc[i * 4 + 1]);
            float2 p2v = upk(acc[i * 4 + 2]);
            float2 p3v = upk(acc[i * 4 + 3]);
            *reinterpret_cast<float4*>(o) = make_float4(p0v.x, p0v.y, p1v.x, p1v.y);
            *reinterpret_cast<float4*>(o + 4) = make_float4(p2v.x, p2v.y, p3v.x, p3v.y);
        }
    }
}

extern "C" void kernel_launch(void* const* d_in, const int* in_sizes, int n_in,
                              void* d_out, int out_size) {
    const float* x = (const float*)d_in[0];
    const float* y = (const float*)d_in[1];
    float* out = (float*)d_out;

    cudaFuncSetAttribute(coex_cost_kernel,
                         cudaFuncAttributeMaxDynamicSharedMemorySize, SMEM_BYTES);

    coex_cost_kernel<<<B_DIM * H_DIM, NTHREADS, SMEM_BYTES>>>(x, y, out);
}

// round 12
// speedup vs baseline: 1.4551x; 1.0395x over previous
#include <cuda_runtime.h>
#include <cstdint>

// CoExCostVolume: cost[b,d,h,w] = sum_c x[b,c,h,w]*y[b,c,h,w-d], zero for w<d.
// B=8, C=96, H=128, W=416, D=49.
//
// One CTA per (b,h) row, 448 threads = 7 warp-pairs; pair g owns d in
// [7g,7g+7), lane index l (<52) owns w in [8l,8l+8).
// XOR swizzle S(p)=p^((p>>3)&4): 16B-alignment preserving, conflict-free for
// the lane-stride-8-float LDS.128 pattern at any 4-aligned base. Every 16B
// vector uses its own swizzled address (SW(w0+4) != SW(w0)+4).
// Compute is SCALAR FFMA: R11 showed packed fma.rn.f32x2 forces register-pair
// marshalling MOVs (~35 alu ops/channel, alu pipe 45%); scalar drops all pair
// constraints, feeding float4 components straight into fmaf.
// cp.async(8B) 3-buffer depth-2 pipeline, 6 chunks of 16 channels, additive
// staging index advance (no div/mod in the staging loop).

#define B_DIM 8
#define C_DIM 96
#define H_DIM 128
#define W_DIM 416
#define D_DIM 49
#define HW (H_DIM * W_DIM)

#define CC 16
#define NC 6
#define NBUF 3
#define XSTRIDE 448
#define YSTRIDE 480
#define XSZ (CC * XSTRIDE)
#define BUFSZ (XSZ + CC * YSTRIDE)
#define NTHREADS 448
#define SMEM_BYTES (NBUF * BUFSZ * 4)   // 178176

__device__ __forceinline__ int SW(int p) { return p ^ ((p >> 3) & 4); }

__device__ __forceinline__ void cp8(float* dst_smem, const float* src) {
    unsigned s = (unsigned)__cvta_generic_to_shared(dst_smem);
    asm volatile("cp.async.ca.shared.global [%0], [%1], 8;\n" ::"r"(s), "l"(src));
}

// One 16-channel chunk. R = q0&3 (warp-uniform window phase).
// Window scalars occupy float offsets [R, R+13] of the 4*NV loaded floats.
template <int R>
__device__ __forceinline__ void accum(const float* __restrict__ buf,
                                      int xo0, int xo1,
                                      const int* __restrict__ yo,
                                      float* __restrict__ acc) {
    constexpr int NV = (R == 3) ? 5 : 4;
#pragma unroll 4
    for (int c = 0; c < CC; c++) {
        float4 xa = *(const float4*)(buf + xo0 + c * XSTRIDE);
        float4 xc = *(const float4*)(buf + xo1 + c * XSTRIDE);
        float xv[8] = {xa.x, xa.y, xa.z, xa.w, xc.x, xc.y, xc.z, xc.w};

        float f[4 * NV];
#pragma unroll
        for (int v = 0; v < NV; v++) {
            float4 q = *(const float4*)(buf + yo[v] + c * YSTRIDE);
            f[4 * v + 0] = q.x; f[4 * v + 1] = q.y;
            f[4 * v + 2] = q.z; f[4 * v + 3] = q.w;
        }

#pragma unroll
        for (int i = 0; i < 7; i++)
#pragma unroll
            for (int j = 0; j < 8; j++)
                acc[i * 8 + j] = fmaf(xv[j], f[R + j + 6 - i], acc[i * 8 + j]);
    }
}

__global__ void __launch_bounds__(NTHREADS, 1)
coex_cost_kernel(const float* __restrict__ x,
                 const float* __restrict__ y,
                 float* __restrict__ out) {
    extern __shared__ float sm[];

    const int bid = blockIdx.x;
    const int b = bid >> 7;
    const int h = bid & 127;
    const int tid = threadIdx.x;
    const int wid = tid >> 5;
    const int lane = tid & 31;
    const int g = wid >> 1;                 // 0..6 d-group (warp-uniform)
    const int l = ((wid & 1) << 5) + lane;  // 0..63
    const bool active = (l < 52);
    const int d0 = 7 * g;
    const int w0 = 8 * l;

    const long rowb = ((long)(b * C_DIM) * H_DIM + h) * W_DIM;

    // ---- zero y left-pad once (all buffers); SW is a bijection on [0,48) ----
    for (int i = tid; i < NBUF * CC * 48; i += NTHREADS) {
        int buf = i / (CC * 48);
        int rest = i - buf * (CC * 48);
        int c = rest / 48;
        int p = rest - c * 48;
        sm[buf * BUFSZ + XSZ + c * YSTRIDE + p] = 0.0f;
    }

    // ---- per-thread addresses ----
    const int w0c = active ? w0 : 0;
    const int q0c = active ? (w0 + 42 - d0) : 0;   // window base, >= 0
    const int R = q0c & 3;                          // warp-uniform
    const int qa = q0c - R;
    const int xo0 = SW(w0c);
    const int xo1 = SW(w0c + 4);                    // own swizzle — NOT xo0+4
    int yo[5];
#pragma unroll
    for (int v = 0; v < 5; v++) yo[v] = XSZ + SW(qa + 4 * v);

    float acc[56];
#pragma unroll
    for (int i = 0; i < 56; i++) acc[i] = 0.0f;

    // ---- staging: additive (c, p) advance, 8B cp.async for x and y ----
    const int c0 = tid / 208;            // 0..2
    const int p0 = tid - c0 * 208;       // float2 index within row
    auto stage = [&](int k) {
        float* bx = sm + (k % NBUF) * BUFSZ;
        float* by = bx + XSZ;
        const float* xg = x + rowb + (long)k * CC * HW;
        const float* yg = y + rowb + (long)k * CC * HW;
        int c = c0, p = p0;
#pragma unroll 1
        for (int it = 0; it < 8; it++) {
            if (c < CC) {
                int w = 2 * p;
                long gsrc = (long)c * HW + w;
                cp8(bx + c * XSTRIDE + SW(w), xg + gsrc);
                cp8(by + c * YSTRIDE + SW(48 + w), yg + gsrc);
            }
            c += 2; p += 32;                 // +448 float2 = 2 rows + 32
            if (p >= 208) { p -= 208; c += 1; }
        }
    };

    stage(0); asm volatile("cp.async.commit_group;\n");
    stage(1); asm volatile("cp.async.commit_group;\n");

#pragma unroll 1
    for (int k = 0; k < NC; k++) {
        if (k < NC - 1) asm volatile("cp.async.wait_group 1;\n" ::: "memory");
        else            asm volatile("cp.async.wait_group 0;\n" ::: "memory");
        __syncthreads();

        if (k + 2 < NC) {
            stage(k + 2);
            asm volatile("cp.async.commit_group;\n");
        }

        const float* buf = sm + (k % NBUF) * BUFSZ;
        if (active) {
            switch (R) {
                case 0: accum<0>(buf, xo0, xo1, yo, acc); break;
                case 1: accum<1>(buf, xo0, xo1, yo, acc); break;
                case 2: accum<2>(buf, xo0, xo1, yo, acc); break;
                default: accum<3>(buf, xo0, xo1, yo, acc); break;
            }
        }
    }

    // ---- stores: 7 d x 8 w per active thread, two float4 per d ----
    if (active) {
#pragma unroll
        for (int i = 0; i < 7; i++) {
            const int d = d0 + i;
            float* o = out + (((long)b * D_DIM + d) * H_DIM + h) * W_DIM + w0;
            *reinterpret_cast<float4*>(o) =
                make_float4(acc[i * 8 + 0], acc[i * 8 + 1], acc[i * 8 + 2], acc[i * 8 + 3]);
            *reinterpret_cast<float4*>(o + 4) =
                make_float4(acc[i * 8 + 4], acc[i * 8 + 5], acc[i * 8 + 6], acc[i * 8 + 7]);
        }
    }
}

extern "C" void kernel_launch(void* const* d_in, const int* in_sizes, int n_in,
                              void* d_out, int out_size) {
    const float* x = (const float*)d_in[0];
    const float* y = (const float*)d_in[1];
    float* out = (float*)d_out;

    cudaFuncSetAttribute(coex_cost_kernel,
                         cudaFuncAttributeMaxDynamicSharedMemorySize, SMEM_BYTES);

    coex_cost_kernel<<<B_DIM * H_DIM, NTHREADS, SMEM_BYTES>>>(x, y, out);
}